// round 6
// baseline (speedup 1.0000x reference)
#include <cuda_runtime.h>
#include <cstdint>

#define NN 100000
#define DD 128
#define NE 1600000
#define BN_EPS 1e-5f

// Scratch (device globals: allocation-free per harness rules).
// float4 => guaranteed 16B alignment for LDG.128/STG.128/RED.v4.
__device__ float4 g_hpre4[(size_t)NN * 32];   // 51.2 MB
__device__ float4 g_h4[(size_t)NN * 32];      // 51.2 MB
__device__ float  g_colsum[DD];
__device__ float  g_colsq[DD];
__device__ float  g_bncoef[2 * DD];           // [0..127]=scale a, [128..255]=shift b
__device__ int    g_is64;                     // edge_index dtype flag

// ---------------------------------------------------------------------------
// Kernel 0: detect edge_index dtype. If the first 16 int64 reads are all in
// [0, NN), the buffer is genuinely int64 (an int32 buffer read as int64 packs
// two random indices; the high word is nonzero w.p. ~1-1e-5 per slot).
// ---------------------------------------------------------------------------
__global__ void detect_kernel(const long long* __restrict__ ei) {
    long long ok = 1;
    #pragma unroll
    for (int i = 0; i < 16; i++) {
        long long v = ei[i];
        if (v < 0 || v >= NN) ok = 0;
    }
    g_is64 = (int)ok;
}

// ---------------------------------------------------------------------------
// Kernel 1: h_pre = (2 + eps) * x ; zero the stat accumulators
// ---------------------------------------------------------------------------
__global__ void init_kernel(const float4* __restrict__ x, const float* __restrict__ eps_p) {
    int i = blockIdx.x * blockDim.x + threadIdx.x;
    float s = 2.0f + *eps_p;
    const int total = NN * 32;
    if (i < total) {
        float4 v = x[i];
        v.x *= s; v.y *= s; v.z *= s; v.w *= s;
        g_hpre4[i] = v;
    }
    if (i < DD) { g_colsum[i] = 0.0f; g_colsq[i] = 0.0f; }
}

// ---------------------------------------------------------------------------
// Kernel 2: edge scatter. One warp per directed edge; lane c handles float4 c.
//   dir 0: h_pre[dst] += x[src];  dir 1: h_pre[src] += x[dst]
// Vector reduction (no return) keeps this pure L2-RMW traffic.
// ---------------------------------------------------------------------------
__global__ void scatter_kernel(const float4* __restrict__ x,
                               const void* __restrict__ ei_raw) {
    long long t = (long long)blockIdx.x * blockDim.x + threadIdx.x;
    int lane = threadIdx.x & 31;
    long long w = t >> 5;
    if (w >= 2LL * NE) return;
    int e; int rev;
    if (w < NE) { e = (int)w; rev = 0; } else { e = (int)(w - NE); rev = 1; }

    long long s, d;
    if (g_is64) {
        const long long* ei = (const long long*)ei_raw;
        s = ei[e];
        d = ei[NE + e];
    } else {
        const int* ei = (const int*)ei_raw;
        s = ei[e];
        d = ei[NE + e];
    }
    long long a = rev ? d : s;
    long long b = rev ? s : d;
    if ((unsigned long long)a >= NN || (unsigned long long)b >= NN) return;

    float4 v = x[a * 32 + lane];
    float4* p = g_hpre4 + (b * 32 + lane);
    asm volatile("red.global.add.v4.f32 [%0], {%1,%2,%3,%4};"
                 :: "l"(p), "f"(v.x), "f"(v.y), "f"(v.z), "f"(v.w) : "memory");
}

// ---------------------------------------------------------------------------
// Kernel 3/5: register-tiled fp32 GEMM  out[N,128] = f(Z[N,128]) @ W^T + bias
//   CTA: 256 threads, tile 128 rows x 128 cols, K=128 fully smem-resident.
//   Micro-tile: warp -> 16 rows, lane -> 4 cols (64 acc / thread).
//   BN_IN:  apply y = relu(a*z + b) while loading the Z tile (GEMM2 path).
//   STATS:  accumulate per-column sum / sumsq of the output (GEMM1 path).
// ---------------------------------------------------------------------------
template <bool BN_IN, bool STATS>
__global__ void __launch_bounds__(256, 1)
gemm_kernel(const float4* __restrict__ Z, const float* __restrict__ W,
            const float* __restrict__ bias, float4* __restrict__ out, int nrows)
{
    extern __shared__ float sm[];
    float* Zs   = sm;                     // [128][132]
    float* Ws   = sm + 128 * 132;         // [128][132], Ws[k*132+j] = W[j][k]
    float* rsum = Ws + 128 * 132;         // [8][128]
    float* rsq  = rsum + 8 * 128;         // [8][128]

    const int tid  = threadIdx.x;
    const int lane = tid & 31;
    const int warp = tid >> 5;
    const int row0 = blockIdx.x * 128;

    // Load W transposed into smem (stride 132 -> conflict-free STS & aligned LDS.128)
    #pragma unroll 8
    for (int idx = tid; idx < 128 * 128; idx += 256) {
        int j = idx >> 7, k = idx & 127;
        Ws[k * 132 + j] = W[idx];
    }

    // Load Z tile (optionally BN+ReLU transformed)
    #pragma unroll 4
    for (int i4 = tid; i4 < 128 * 32; i4 += 256) {
        int r = i4 >> 5, c4 = i4 & 31;
        int row = row0 + r;
        float4 v = make_float4(0.f, 0.f, 0.f, 0.f);
        if (row < nrows) {
            v = Z[(size_t)row * 32 + c4];
            if (BN_IN) {
                int c = c4 * 4;
                v.x = fmaxf(fmaf(g_bncoef[c + 0], v.x, g_bncoef[DD + c + 0]), 0.f);
                v.y = fmaxf(fmaf(g_bncoef[c + 1], v.y, g_bncoef[DD + c + 1]), 0.f);
                v.z = fmaxf(fmaf(g_bncoef[c + 2], v.z, g_bncoef[DD + c + 2]), 0.f);
                v.w = fmaxf(fmaf(g_bncoef[c + 3], v.w, g_bncoef[DD + c + 3]), 0.f);
            }
        }
        *reinterpret_cast<float4*>(&Zs[r * 132 + c4 * 4]) = v;
    }
    __syncthreads();

    float4 acc[16];
    #pragma unroll
    for (int i = 0; i < 16; i++) acc[i] = make_float4(0.f, 0.f, 0.f, 0.f);

    const float* zbase = Zs + (warp * 16) * 132;
    #pragma unroll 4
    for (int k = 0; k < 128; k++) {
        float4 bv = *reinterpret_cast<const float4*>(&Ws[k * 132 + lane * 4]);
        #pragma unroll
        for (int i = 0; i < 16; i++) {
            float av = zbase[i * 132 + k];       // broadcast within warp
            acc[i].x = fmaf(av, bv.x, acc[i].x);
            acc[i].y = fmaf(av, bv.y, acc[i].y);
            acc[i].z = fmaf(av, bv.z, acc[i].z);
            acc[i].w = fmaf(av, bv.w, acc[i].w);
        }
    }

    float4 bb = *reinterpret_cast<const float4*>(&bias[lane * 4]);

    float4 s  = make_float4(0.f, 0.f, 0.f, 0.f);
    float4 s2 = make_float4(0.f, 0.f, 0.f, 0.f);
    #pragma unroll
    for (int i = 0; i < 16; i++) {
        int row = row0 + warp * 16 + i;
        if (row < nrows) {
            float4 o;
            o.x = acc[i].x + bb.x;
            o.y = acc[i].y + bb.y;
            o.z = acc[i].z + bb.z;
            o.w = acc[i].w + bb.w;
            out[(size_t)row * 32 + lane] = o;
            if (STATS) {
                s.x += o.x; s.y += o.y; s.z += o.z; s.w += o.w;
                s2.x += o.x * o.x; s2.y += o.y * o.y;
                s2.z += o.z * o.z; s2.w += o.w * o.w;
            }
        }
    }

    if (STATS) {
        *reinterpret_cast<float4*>(&rsum[warp * 128 + lane * 4]) = s;
        *reinterpret_cast<float4*>(&rsq[warp * 128 + lane * 4])  = s2;
        __syncthreads();
        if (tid < 128) {
            float a = 0.f, b2 = 0.f;
            #pragma unroll
            for (int w = 0; w < 8; w++) {
                a  += rsum[w * 128 + tid];
                b2 += rsq[w * 128 + tid];
            }
            atomicAdd(&g_colsum[tid], a);
            atomicAdd(&g_colsq[tid], b2);
        }
    }
}

// ---------------------------------------------------------------------------
// Kernel 4: fold BN into y = a*h + b
// ---------------------------------------------------------------------------
__global__ void bn_finalize(const float* __restrict__ gamma, const float* __restrict__ beta) {
    int j = threadIdx.x;
    float invn = 1.0f / (float)NN;
    float mean = g_colsum[j] * invn;
    float var  = g_colsq[j] * invn - mean * mean;
    float a = gamma[j] * rsqrtf(var + BN_EPS);
    g_bncoef[j]      = a;
    g_bncoef[DD + j] = beta[j] - mean * a;
}

// ---------------------------------------------------------------------------
extern "C" void kernel_launch(void* const* d_in, const int* in_sizes, int n_in,
                              void* d_out, int out_size) {
    const float* x     = (const float*)d_in[0];
    const void*  ei    = d_in[1];
    const float* eps   = (const float*)d_in[2];
    const float* W1    = (const float*)d_in[3];
    const float* b1    = (const float*)d_in[4];
    const float* gamma = (const float*)d_in[5];
    const float* beta  = (const float*)d_in[6];
    const float* W2    = (const float*)d_in[7];
    const float* b2    = (const float*)d_in[8];

    void* hpre_p = nullptr;
    void* h_p    = nullptr;
    cudaGetSymbolAddress(&hpre_p, g_hpre4);
    cudaGetSymbolAddress(&h_p, g_h4);
    const float4* hpre4 = (const float4*)hpre_p;
    const float4* h4    = (const float4*)h_p;

    const int SMEM = (128 * 132 * 2 + 2 * 8 * 128) * (int)sizeof(float); // 143360
    cudaFuncSetAttribute(gemm_kernel<false, true>,
                         cudaFuncAttributeMaxDynamicSharedMemorySize, SMEM);
    cudaFuncSetAttribute(gemm_kernel<true, false>,
                         cudaFuncAttributeMaxDynamicSharedMemorySize, SMEM);

    // 0) detect edge_index dtype (int32 vs int64)
    detect_kernel<<<1, 1>>>((const long long*)ei);
    // 1) h_pre = (2+eps)*x, zero stats
    {
        int total = NN * 32;
        int blocks = (total + 255) / 256;
        init_kernel<<<blocks, 256>>>((const float4*)x, eps);
    }
    // 2) scatter-add both directions
    {
        long long threads = 2LL * NE * 32;
        int blocks = (int)((threads + 255) / 256);
        scatter_kernel<<<blocks, 256>>>((const float4*)x, ei);
    }
    // 3) GEMM1 (+bias, +column stats) : g_h = g_hpre @ W1^T + b1
    {
        int blocks = (NN + 127) / 128;
        gemm_kernel<false, true><<<blocks, 256, SMEM>>>(hpre4, W1, b1, (float4*)h_p, NN);
    }
    // 4) BN coefficients
    bn_finalize<<<1, DD>>>(gamma, beta);
    // 5) GEMM2 (+BN+ReLU on input) : out = relu(a*g_h+b) @ W2^T + b2
    {
        int blocks = (NN + 127) / 128;
        gemm_kernel<true, false><<<blocks, 256, SMEM>>>(h4, W2, b2, (float4*)d_out, NN);
    }
}

// round 9
// speedup vs baseline: 1.8060x; 1.8060x over previous
#include <cuda_runtime.h>
#include <cstdint>

#define NN 100000
#define DD 128
#define NE 1600000
#define BN_EPS 1e-5f
#define SCAN_B 512
#define NBLK1 ((NN + SCAN_B - 1) / SCAN_B)   // 196

// Scratch (device globals; float4 => 16B alignment for LDG/STG.128)
__device__ float4 g_hpre4[(size_t)NN * 32];   // 51.2 MB
__device__ float4 g_h4[(size_t)NN * 32];      // 51.2 MB
__device__ float  g_colsum[DD];
__device__ float  g_colsq[DD];
__device__ float  g_bncoef[2 * DD];
__device__ int    g_is64;
// CSR scratch
__device__ int    g_deg[NN];
__device__ int    g_off[NN];
__device__ int    g_cur[NN];
__device__ int    g_adj[2 * NE];              // 12.8 MB
__device__ int    g_bsum[NBLK1];
__device__ int    g_bpre[NBLK1];

// ---------------------------------------------------------------------------
// dtype detect: 16 in-range int64 reads => genuinely int64
// ---------------------------------------------------------------------------
__global__ void detect_kernel(const long long* __restrict__ ei) {
    long long ok = 1;
    #pragma unroll
    for (int i = 0; i < 16; i++) {
        long long v = ei[i];
        if (v < 0 || v >= NN) ok = 0;
    }
    g_is64 = (int)ok;
}

__device__ __forceinline__ void load_edge(const void* ei_raw, int e, int& s, int& d) {
    if (g_is64) {
        const long long* ei = (const long long*)ei_raw;
        s = (int)ei[e]; d = (int)ei[NE + e];
    } else {
        const int* ei = (const int*)ei_raw;
        s = ei[e]; d = ei[NE + e];
    }
}

// ---------------------------------------------------------------------------
// zero degrees + BN stat accumulators
// ---------------------------------------------------------------------------
__global__ void zero_kernel() {
    int i = blockIdx.x * blockDim.x + threadIdx.x;
    if (i < NN) g_deg[i] = 0;
    if (i < DD) { g_colsum[i] = 0.0f; g_colsq[i] = 0.0f; }
}

// ---------------------------------------------------------------------------
// degree histogram: each edge contributes dst<-src and src<-dst
// ---------------------------------------------------------------------------
__global__ void hist_kernel(const void* __restrict__ ei_raw) {
    int e = blockIdx.x * blockDim.x + threadIdx.x;
    if (e >= NE) return;
    int s, d; load_edge(ei_raw, e, s, d);
    atomicAdd(&g_deg[d], 1);
    atomicAdd(&g_deg[s], 1);
}

// ---------------------------------------------------------------------------
// two-level exclusive scan of g_deg -> g_off (and g_cur copy)
// ---------------------------------------------------------------------------
__global__ void scan_block_kernel() {
    __shared__ int sh[SCAN_B];
    int tid = threadIdx.x;
    int i = blockIdx.x * SCAN_B + tid;
    int v = (i < NN) ? g_deg[i] : 0;
    sh[tid] = v;
    __syncthreads();
    #pragma unroll
    for (int o = 1; o < SCAN_B; o <<= 1) {
        int t = (tid >= o) ? sh[tid - o] : 0;
        __syncthreads();
        sh[tid] += t;
        __syncthreads();
    }
    if (i < NN) g_off[i] = sh[tid] - v;          // local exclusive
    if (tid == SCAN_B - 1) g_bsum[blockIdx.x] = sh[tid];
}

__global__ void scan_top_kernel() {
    __shared__ int sh[256];
    int tid = threadIdx.x;
    int v = (tid < NBLK1) ? g_bsum[tid] : 0;
    sh[tid] = v;
    __syncthreads();
    #pragma unroll
    for (int o = 1; o < 256; o <<= 1) {
        int t = (tid >= o) ? sh[tid - o] : 0;
        __syncthreads();
        sh[tid] += t;
        __syncthreads();
    }
    if (tid < NBLK1) g_bpre[tid] = sh[tid] - v;  // exclusive block prefix
}

__global__ void scan_add_kernel() {
    int i = blockIdx.x * SCAN_B + threadIdx.x;
    if (i < NN) {
        int o = g_off[i] + g_bpre[blockIdx.x];
        g_off[i] = o;
        g_cur[i] = o;
    }
}

// ---------------------------------------------------------------------------
// adjacency fill (order within a list is irrelevant for a sum)
// ---------------------------------------------------------------------------
__global__ void fill_kernel(const void* __restrict__ ei_raw) {
    int e = blockIdx.x * blockDim.x + threadIdx.x;
    if (e >= NE) return;
    int s, d; load_edge(ei_raw, e, s, d);
    int p0 = atomicAdd(&g_cur[d], 1);
    g_adj[p0] = s;
    int p1 = atomicAdd(&g_cur[s], 1);
    g_adj[p1] = d;
}

// ---------------------------------------------------------------------------
// gather: one warp per node.  hpre[n] = (2+eps)*x[n] + sum_nbr x[nbr]
// lane c owns float4 chunk c of the 128-float row.
// ---------------------------------------------------------------------------
__global__ void gather_kernel(const float4* __restrict__ x,
                              const float* __restrict__ eps_p) {
    int w = (blockIdx.x * blockDim.x + threadIdx.x) >> 5;
    if (w >= NN) return;
    int lane = threadIdx.x & 31;
    float sc = 2.0f + *eps_p;

    float4 xv = x[(size_t)w * 32 + lane];
    float4 acc = make_float4(xv.x * sc, xv.y * sc, xv.z * sc, xv.w * sc);

    int off = g_off[w];
    int deg = g_deg[w];
    int i = 0;
    for (; i + 4 <= deg; i += 4) {
        int n0 = g_adj[off + i + 0];
        int n1 = g_adj[off + i + 1];
        int n2 = g_adj[off + i + 2];
        int n3 = g_adj[off + i + 3];
        float4 v0 = x[(size_t)n0 * 32 + lane];
        float4 v1 = x[(size_t)n1 * 32 + lane];
        float4 v2 = x[(size_t)n2 * 32 + lane];
        float4 v3 = x[(size_t)n3 * 32 + lane];
        acc.x += v0.x + v1.x + v2.x + v3.x;
        acc.y += v0.y + v1.y + v2.y + v3.y;
        acc.z += v0.z + v1.z + v2.z + v3.z;
        acc.w += v0.w + v1.w + v2.w + v3.w;
    }
    for (; i < deg; i++) {
        int n0 = g_adj[off + i];
        float4 v0 = x[(size_t)n0 * 32 + lane];
        acc.x += v0.x; acc.y += v0.y; acc.z += v0.z; acc.w += v0.w;
    }
    g_hpre4[(size_t)w * 32 + lane] = acc;
}

// ---------------------------------------------------------------------------
// register-tiled fp32 GEMM  out[N,128] = f(Z[N,128]) @ W^T + bias
//   512 threads (16 warps). Tile 128 rows x 128 cols, K=128 smem-resident.
//   warp -> 8 rows, lane -> 4 cols (32 acc/thread). Z read as float4 along k.
// ---------------------------------------------------------------------------
template <bool BN_IN, bool STATS>
__global__ void __launch_bounds__(512, 1)
gemm_kernel(const float4* __restrict__ Z, const float* __restrict__ W,
            const float* __restrict__ bias, float4* __restrict__ out, int nrows)
{
    extern __shared__ float sm[];
    float* Zs   = sm;                     // [128][132]
    float* Ws   = sm + 128 * 132;         // [128][132], Ws[k*132+j] = W[j][k]
    float* rsum = Ws + 128 * 132;         // [16][128]
    float* rsq  = rsum + 16 * 128;        // [16][128]

    const int tid  = threadIdx.x;
    const int lane = tid & 31;
    const int warp = tid >> 5;
    const int row0 = blockIdx.x * 128;

    // W transposed into smem (stride 132 -> conflict-free, 16B-aligned rows)
    #pragma unroll 8
    for (int idx = tid; idx < 128 * 128; idx += 512) {
        int j = idx >> 7, k = idx & 127;
        Ws[k * 132 + j] = W[idx];
    }

    // Z tile (optionally BN+ReLU transformed)
    #pragma unroll 8
    for (int i4 = tid; i4 < 128 * 32; i4 += 512) {
        int r = i4 >> 5, c4 = i4 & 31;
        int row = row0 + r;
        float4 v = make_float4(0.f, 0.f, 0.f, 0.f);
        if (row < nrows) {
            v = Z[(size_t)row * 32 + c4];
            if (BN_IN) {
                int c = c4 * 4;
                v.x = fmaxf(fmaf(g_bncoef[c + 0], v.x, g_bncoef[DD + c + 0]), 0.f);
                v.y = fmaxf(fmaf(g_bncoef[c + 1], v.y, g_bncoef[DD + c + 1]), 0.f);
                v.z = fmaxf(fmaf(g_bncoef[c + 2], v.z, g_bncoef[DD + c + 2]), 0.f);
                v.w = fmaxf(fmaf(g_bncoef[c + 3], v.w, g_bncoef[DD + c + 3]), 0.f);
            }
        }
        *reinterpret_cast<float4*>(&Zs[r * 132 + c4 * 4]) = v;
    }
    __syncthreads();

    float4 acc[8];
    #pragma unroll
    for (int i = 0; i < 8; i++) acc[i] = make_float4(0.f, 0.f, 0.f, 0.f);

    const float* zbase = Zs + (warp * 8) * 132;
    #pragma unroll 2
    for (int k = 0; k < 128; k += 4) {
        float4 z[8];
        #pragma unroll
        for (int i = 0; i < 8; i++)
            z[i] = *reinterpret_cast<const float4*>(&zbase[i * 132 + k]);  // broadcast
        #pragma unroll
        for (int kk = 0; kk < 4; kk++) {
            float4 bv = *reinterpret_cast<const float4*>(&Ws[(k + kk) * 132 + lane * 4]);
            #pragma unroll
            for (int i = 0; i < 8; i++) {
                float av = (kk == 0) ? z[i].x : (kk == 1) ? z[i].y : (kk == 2) ? z[i].z : z[i].w;
                acc[i].x = fmaf(av, bv.x, acc[i].x);
                acc[i].y = fmaf(av, bv.y, acc[i].y);
                acc[i].z = fmaf(av, bv.z, acc[i].z);
                acc[i].w = fmaf(av, bv.w, acc[i].w);
            }
        }
    }

    float4 bb = *reinterpret_cast<const float4*>(&bias[lane * 4]);

    float4 s  = make_float4(0.f, 0.f, 0.f, 0.f);
    float4 s2 = make_float4(0.f, 0.f, 0.f, 0.f);
    #pragma unroll
    for (int i = 0; i < 8; i++) {
        int row = row0 + warp * 8 + i;
        if (row < nrows) {
            float4 o;
            o.x = acc[i].x + bb.x;
            o.y = acc[i].y + bb.y;
            o.z = acc[i].z + bb.z;
            o.w = acc[i].w + bb.w;
            out[(size_t)row * 32 + lane] = o;
            if (STATS) {
                s.x += o.x; s.y += o.y; s.z += o.z; s.w += o.w;
                s2.x += o.x * o.x; s2.y += o.y * o.y;
                s2.z += o.z * o.z; s2.w += o.w * o.w;
            }
        }
    }

    if (STATS) {
        *reinterpret_cast<float4*>(&rsum[warp * 128 + lane * 4]) = s;
        *reinterpret_cast<float4*>(&rsq[warp * 128 + lane * 4])  = s2;
        __syncthreads();
        if (tid < 128) {
            float a = 0.f, b2 = 0.f;
            #pragma unroll
            for (int w = 0; w < 16; w++) {
                a  += rsum[w * 128 + tid];
                b2 += rsq[w * 128 + tid];
            }
            atomicAdd(&g_colsum[tid], a);
            atomicAdd(&g_colsq[tid], b2);
        }
    }
}

// ---------------------------------------------------------------------------
__global__ void bn_finalize(const float* __restrict__ gamma, const float* __restrict__ beta) {
    int j = threadIdx.x;
    float invn = 1.0f / (float)NN;
    float mean = g_colsum[j] * invn;
    float var  = g_colsq[j] * invn - mean * mean;
    float a = gamma[j] * rsqrtf(var + BN_EPS);
    g_bncoef[j]      = a;
    g_bncoef[DD + j] = beta[j] - mean * a;
}

// ---------------------------------------------------------------------------
extern "C" void kernel_launch(void* const* d_in, const int* in_sizes, int n_in,
                              void* d_out, int out_size) {
    const float* x     = (const float*)d_in[0];
    const void*  ei    = d_in[1];
    const float* eps   = (const float*)d_in[2];
    const float* W1    = (const float*)d_in[3];
    const float* b1    = (const float*)d_in[4];
    const float* gamma = (const float*)d_in[5];
    const float* beta  = (const float*)d_in[6];
    const float* W2    = (const float*)d_in[7];
    const float* b2    = (const float*)d_in[8];

    void* hpre_p = nullptr;
    void* h_p    = nullptr;
    cudaGetSymbolAddress(&hpre_p, g_hpre4);
    cudaGetSymbolAddress(&h_p, g_h4);
    const float4* hpre4 = (const float4*)hpre_p;
    const float4* h4    = (const float4*)h_p;

    const int SMEM = (128 * 132 * 2 + 2 * 16 * 128) * (int)sizeof(float); // 151552
    cudaFuncSetAttribute(gemm_kernel<false, true>,
                         cudaFuncAttributeMaxDynamicSharedMemorySize, SMEM);
    cudaFuncSetAttribute(gemm_kernel<true, false>,
                         cudaFuncAttributeMaxDynamicSharedMemorySize, SMEM);

    // 0) dtype detect + zero
    detect_kernel<<<1, 1>>>((const long long*)ei);
    zero_kernel<<<(NN + 255) / 256, 256>>>();
    // 1) CSR build
    hist_kernel<<<(NE + 255) / 256, 256>>>(ei);
    scan_block_kernel<<<NBLK1, SCAN_B>>>();
    scan_top_kernel<<<1, 256>>>();
    scan_add_kernel<<<NBLK1, SCAN_B>>>();
    fill_kernel<<<(NE + 255) / 256, 256>>>(ei);
    // 2) gather: hpre = (2+eps)x + neighbor sum
    gather_kernel<<<(NN * 32 + 255) / 256, 256>>>((const float4*)x, eps);
    // 3) GEMM1 (+bias, +column stats)
    {
        int blocks = (NN + 127) / 128;
        gemm_kernel<false, true><<<blocks, 512, SMEM>>>(hpre4, W1, b1, (float4*)h_p, NN);
    }
    // 4) BN coefficients
    bn_finalize<<<1, DD>>>(gamma, beta);
    // 5) GEMM2 (+BN+ReLU on input)
    {
        int blocks = (NN + 127) / 128;
        gemm_kernel<true, false><<<blocks, 512, SMEM>>>(h4, W2, b2, (float4*)d_out, NN);
    }
}

// round 11
// speedup vs baseline: 1.8269x; 1.0116x over previous
#include <cuda_runtime.h>
#include <cuda_fp16.h>
#include <cstdint>

#define NN 100000
#define DD 128
#define NE 1600000
#define BN_EPS 1e-5f
#define SCAN_B 512
#define NBLK1 ((NN + SCAN_B - 1) / SCAN_B)   // 196

// Scratch (device globals; float4/uint2 => alignment for wide ld/st)
__device__ float4 g_hpre4[(size_t)NN * 32];   // 51.2 MB
__device__ float4 g_h4[(size_t)NN * 32];      // 51.2 MB
__device__ uint2  g_xh2[(size_t)NN * 32];     // 25.6 MB fp16 mirror of x (4 halves/entry)
__device__ float  g_colsum[DD];
__device__ float  g_colsq[DD];
__device__ float  g_bncoef[2 * DD];
__device__ int    g_is64;
// CSR scratch
__device__ int    g_deg[NN];
__device__ int    g_off[NN];
__device__ int    g_cur[NN];
__device__ int    g_adj[2 * NE];              // 12.8 MB
__device__ int    g_bsum[NBLK1];
__device__ int    g_bpre[NBLK1];

// ---------------------------------------------------------------------------
// dtype detect: 16 in-range int64 reads => genuinely int64
// ---------------------------------------------------------------------------
__global__ void detect_kernel(const long long* __restrict__ ei) {
    long long ok = 1;
    #pragma unroll
    for (int i = 0; i < 16; i++) {
        long long v = ei[i];
        if (v < 0 || v >= NN) ok = 0;
    }
    g_is64 = (int)ok;
}

__device__ __forceinline__ void load_edge(const void* ei_raw, int e, int& s, int& d) {
    if (g_is64) {
        const long long* ei = (const long long*)ei_raw;
        s = (int)ei[e]; d = (int)ei[NE + e];
    } else {
        const int* ei = (const int*)ei_raw;
        s = ei[e]; d = ei[NE + e];
    }
}

// ---------------------------------------------------------------------------
// zero degrees + BN stat accumulators
// ---------------------------------------------------------------------------
__global__ void zero_kernel() {
    int i = blockIdx.x * blockDim.x + threadIdx.x;
    if (i < NN) g_deg[i] = 0;
    if (i < DD) { g_colsum[i] = 0.0f; g_colsq[i] = 0.0f; }
}

// ---------------------------------------------------------------------------
// fp16 mirror of x:  g_xh2[i] packs x[i] (float4) as 4 halves
// ---------------------------------------------------------------------------
__global__ void convert_kernel(const float4* __restrict__ x) {
    int i = blockIdx.x * blockDim.x + threadIdx.x;
    if (i >= NN * 32) return;
    float4 v = x[i];
    half2 lo = __floats2half2_rn(v.x, v.y);
    half2 hi = __floats2half2_rn(v.z, v.w);
    uint2 u;
    u.x = *reinterpret_cast<unsigned int*>(&lo);
    u.y = *reinterpret_cast<unsigned int*>(&hi);
    g_xh2[i] = u;
}

// ---------------------------------------------------------------------------
// degree histogram
// ---------------------------------------------------------------------------
__global__ void hist_kernel(const void* __restrict__ ei_raw) {
    int e = blockIdx.x * blockDim.x + threadIdx.x;
    if (e >= NE) return;
    int s, d; load_edge(ei_raw, e, s, d);
    atomicAdd(&g_deg[d], 1);
    atomicAdd(&g_deg[s], 1);
}

// ---------------------------------------------------------------------------
// two-level exclusive scan of g_deg -> g_off (and g_cur copy)
// ---------------------------------------------------------------------------
__global__ void scan_block_kernel() {
    __shared__ int sh[SCAN_B];
    int tid = threadIdx.x;
    int i = blockIdx.x * SCAN_B + tid;
    int v = (i < NN) ? g_deg[i] : 0;
    sh[tid] = v;
    __syncthreads();
    #pragma unroll
    for (int o = 1; o < SCAN_B; o <<= 1) {
        int t = (tid >= o) ? sh[tid - o] : 0;
        __syncthreads();
        sh[tid] += t;
        __syncthreads();
    }
    if (i < NN) g_off[i] = sh[tid] - v;
    if (tid == SCAN_B - 1) g_bsum[blockIdx.x] = sh[tid];
}

__global__ void scan_top_kernel() {
    __shared__ int sh[256];
    int tid = threadIdx.x;
    int v = (tid < NBLK1) ? g_bsum[tid] : 0;
    sh[tid] = v;
    __syncthreads();
    #pragma unroll
    for (int o = 1; o < 256; o <<= 1) {
        int t = (tid >= o) ? sh[tid - o] : 0;
        __syncthreads();
        sh[tid] += t;
        __syncthreads();
    }
    if (tid < NBLK1) g_bpre[tid] = sh[tid] - v;
}

__global__ void scan_add_kernel() {
    int i = blockIdx.x * SCAN_B + threadIdx.x;
    if (i < NN) {
        int o = g_off[i] + g_bpre[blockIdx.x];
        g_off[i] = o;
        g_cur[i] = o;
    }
}

// ---------------------------------------------------------------------------
// adjacency fill
// ---------------------------------------------------------------------------
__global__ void fill_kernel(const void* __restrict__ ei_raw) {
    int e = blockIdx.x * blockDim.x + threadIdx.x;
    if (e >= NE) return;
    int s, d; load_edge(ei_raw, e, s, d);
    int p0 = atomicAdd(&g_cur[d], 1);
    g_adj[p0] = s;
    int p1 = atomicAdd(&g_cur[s], 1);
    g_adj[p1] = d;
}

// ---------------------------------------------------------------------------
// gather: one warp per node.  hpre[n] = (2+eps)*x[n] + sum_nbr xh[nbr]
// Neighbor rows are fp16 (256B): lane c owns 4 halves (uint2).  Self term
// stays exact fp32.  Accumulation fp32.
// ---------------------------------------------------------------------------
__global__ void gather_kernel(const float4* __restrict__ x,
                              const float* __restrict__ eps_p) {
    int w = (blockIdx.x * blockDim.x + threadIdx.x) >> 5;
    if (w >= NN) return;
    int lane = threadIdx.x & 31;
    float sc = 2.0f + *eps_p;

    float4 xv = x[(size_t)w * 32 + lane];
    float4 acc = make_float4(xv.x * sc, xv.y * sc, xv.z * sc, xv.w * sc);

    int off = g_off[w];
    int deg = g_deg[w];
    int i = 0;
    for (; i + 4 <= deg; i += 4) {
        int n0 = g_adj[off + i + 0];
        int n1 = g_adj[off + i + 1];
        int n2 = g_adj[off + i + 2];
        int n3 = g_adj[off + i + 3];
        uint2 u0 = g_xh2[(size_t)n0 * 32 + lane];
        uint2 u1 = g_xh2[(size_t)n1 * 32 + lane];
        uint2 u2 = g_xh2[(size_t)n2 * 32 + lane];
        uint2 u3 = g_xh2[(size_t)n3 * 32 + lane];
        float2 a0 = __half22float2(*reinterpret_cast<half2*>(&u0.x));
        float2 b0 = __half22float2(*reinterpret_cast<half2*>(&u0.y));
        float2 a1 = __half22float2(*reinterpret_cast<half2*>(&u1.x));
        float2 b1 = __half22float2(*reinterpret_cast<half2*>(&u1.y));
        float2 a2 = __half22float2(*reinterpret_cast<half2*>(&u2.x));
        float2 b2 = __half22float2(*reinterpret_cast<half2*>(&u2.y));
        float2 a3 = __half22float2(*reinterpret_cast<half2*>(&u3.x));
        float2 b3 = __half22float2(*reinterpret_cast<half2*>(&u3.y));
        acc.x += (a0.x + a1.x) + (a2.x + a3.x);
        acc.y += (a0.y + a1.y) + (a2.y + a3.y);
        acc.z += (b0.x + b1.x) + (b2.x + b3.x);
        acc.w += (b0.y + b1.y) + (b2.y + b3.y);
    }
    for (; i < deg; i++) {
        int n0 = g_adj[off + i];
        uint2 u0 = g_xh2[(size_t)n0 * 32 + lane];
        float2 a0 = __half22float2(*reinterpret_cast<half2*>(&u0.x));
        float2 b0 = __half22float2(*reinterpret_cast<half2*>(&u0.y));
        acc.x += a0.x; acc.y += a0.y; acc.z += b0.x; acc.w += b0.y;
    }
    g_hpre4[(size_t)w * 32 + lane] = acc;
}

// ---------------------------------------------------------------------------
// register-tiled fp32 GEMM  out[N,128] = f(Z[N,128]) @ W^T + bias
// 512 threads (16 warps); tile 128x128, K=128 smem-resident.
// ---------------------------------------------------------------------------
template <bool BN_IN, bool STATS>
__global__ void __launch_bounds__(512, 1)
gemm_kernel(const float4* __restrict__ Z, const float* __restrict__ W,
            const float* __restrict__ bias, float4* __restrict__ out, int nrows)
{
    extern __shared__ float sm[];
    float* Zs   = sm;                     // [128][132]
    float* Ws   = sm + 128 * 132;         // [128][132], Ws[k*132+j] = W[j][k]
    float* rsum = Ws + 128 * 132;         // [16][128]
    float* rsq  = rsum + 16 * 128;        // [16][128]

    const int tid  = threadIdx.x;
    const int lane = tid & 31;
    const int warp = tid >> 5;
    const int row0 = blockIdx.x * 128;

    #pragma unroll 8
    for (int idx = tid; idx < 128 * 128; idx += 512) {
        int j = idx >> 7, k = idx & 127;
        Ws[k * 132 + j] = W[idx];
    }

    #pragma unroll 8
    for (int i4 = tid; i4 < 128 * 32; i4 += 512) {
        int r = i4 >> 5, c4 = i4 & 31;
        int row = row0 + r;
        float4 v = make_float4(0.f, 0.f, 0.f, 0.f);
        if (row < nrows) {
            v = Z[(size_t)row * 32 + c4];
            if (BN_IN) {
                int c = c4 * 4;
                v.x = fmaxf(fmaf(g_bncoef[c + 0], v.x, g_bncoef[DD + c + 0]), 0.f);
                v.y = fmaxf(fmaf(g_bncoef[c + 1], v.y, g_bncoef[DD + c + 1]), 0.f);
                v.z = fmaxf(fmaf(g_bncoef[c + 2], v.z, g_bncoef[DD + c + 2]), 0.f);
                v.w = fmaxf(fmaf(g_bncoef[c + 3], v.w, g_bncoef[DD + c + 3]), 0.f);
            }
        }
        *reinterpret_cast<float4*>(&Zs[r * 132 + c4 * 4]) = v;
    }
    __syncthreads();

    float4 acc[8];
    #pragma unroll
    for (int i = 0; i < 8; i++) acc[i] = make_float4(0.f, 0.f, 0.f, 0.f);

    const float* zbase = Zs + (warp * 8) * 132;
    #pragma unroll 2
    for (int k = 0; k < 128; k += 4) {
        float4 z[8];
        #pragma unroll
        for (int i = 0; i < 8; i++)
            z[i] = *reinterpret_cast<const float4*>(&zbase[i * 132 + k]);
        #pragma unroll
        for (int kk = 0; kk < 4; kk++) {
            float4 bv = *reinterpret_cast<const float4*>(&Ws[(k + kk) * 132 + lane * 4]);
            #pragma unroll
            for (int i = 0; i < 8; i++) {
                float av = (kk == 0) ? z[i].x : (kk == 1) ? z[i].y : (kk == 2) ? z[i].z : z[i].w;
                acc[i].x = fmaf(av, bv.x, acc[i].x);
                acc[i].y = fmaf(av, bv.y, acc[i].y);
                acc[i].z = fmaf(av, bv.z, acc[i].z);
                acc[i].w = fmaf(av, bv.w, acc[i].w);
            }
        }
    }

    float4 bb = *reinterpret_cast<const float4*>(&bias[lane * 4]);

    float4 s  = make_float4(0.f, 0.f, 0.f, 0.f);
    float4 s2 = make_float4(0.f, 0.f, 0.f, 0.f);
    #pragma unroll
    for (int i = 0; i < 8; i++) {
        int row = row0 + warp * 8 + i;
        if (row < nrows) {
            float4 o;
            o.x = acc[i].x + bb.x;
            o.y = acc[i].y + bb.y;
            o.z = acc[i].z + bb.z;
            o.w = acc[i].w + bb.w;
            out[(size_t)row * 32 + lane] = o;
            if (STATS) {
                s.x += o.x; s.y += o.y; s.z += o.z; s.w += o.w;
                s2.x += o.x * o.x; s2.y += o.y * o.y;
                s2.z += o.z * o.z; s2.w += o.w * o.w;
            }
        }
    }

    if (STATS) {
        *reinterpret_cast<float4*>(&rsum[warp * 128 + lane * 4]) = s;
        *reinterpret_cast<float4*>(&rsq[warp * 128 + lane * 4])  = s2;
        __syncthreads();
        if (tid < 128) {
            float a = 0.f, b2 = 0.f;
            #pragma unroll
            for (int w = 0; w < 16; w++) {
                a  += rsum[w * 128 + tid];
                b2 += rsq[w * 128 + tid];
            }
            atomicAdd(&g_colsum[tid], a);
            atomicAdd(&g_colsq[tid], b2);
        }
    }
}

// ---------------------------------------------------------------------------
__global__ void bn_finalize(const float* __restrict__ gamma, const float* __restrict__ beta) {
    int j = threadIdx.x;
    float invn = 1.0f / (float)NN;
    float mean = g_colsum[j] * invn;
    float var  = g_colsq[j] * invn - mean * mean;
    float a = gamma[j] * rsqrtf(var + BN_EPS);
    g_bncoef[j]      = a;
    g_bncoef[DD + j] = beta[j] - mean * a;
}

// ---------------------------------------------------------------------------
extern "C" void kernel_launch(void* const* d_in, const int* in_sizes, int n_in,
                              void* d_out, int out_size) {
    const float* x     = (const float*)d_in[0];
    const void*  ei    = d_in[1];
    const float* eps   = (const float*)d_in[2];
    const float* W1    = (const float*)d_in[3];
    const float* b1    = (const float*)d_in[4];
    const float* gamma = (const float*)d_in[5];
    const float* beta  = (const float*)d_in[6];
    const float* W2    = (const float*)d_in[7];
    const float* b2    = (const float*)d_in[8];

    void* hpre_p = nullptr;
    void* h_p    = nullptr;
    cudaGetSymbolAddress(&hpre_p, g_hpre4);
    cudaGetSymbolAddress(&h_p, g_h4);
    const float4* hpre4 = (const float4*)hpre_p;
    const float4* h4    = (const float4*)h_p;

    const int SMEM = (128 * 132 * 2 + 2 * 16 * 128) * (int)sizeof(float); // 151552
    cudaFuncSetAttribute(gemm_kernel<false, true>,
                         cudaFuncAttributeMaxDynamicSharedMemorySize, SMEM);
    cudaFuncSetAttribute(gemm_kernel<true, false>,
                         cudaFuncAttributeMaxDynamicSharedMemorySize, SMEM);

    // 0) dtype detect + zero + fp16 mirror of x
    detect_kernel<<<1, 1>>>((const long long*)ei);
    zero_kernel<<<(NN + 255) / 256, 256>>>();
    convert_kernel<<<(NN * 32 + 255) / 256, 256>>>((const float4*)x);
    // 1) CSR build
    hist_kernel<<<(NE + 255) / 256, 256>>>(ei);
    scan_block_kernel<<<NBLK1, SCAN_B>>>();
    scan_top_kernel<<<1, 256>>>();
    scan_add_kernel<<<NBLK1, SCAN_B>>>();
    fill_kernel<<<(NE + 255) / 256, 256>>>(ei);
    // 2) gather: hpre = (2+eps)x + neighbor sum (fp16 reads, fp32 accum)
    gather_kernel<<<(NN * 32 + 255) / 256, 256>>>((const float4*)x, eps);
    // 3) GEMM1 (+bias, +column stats)
    {
        int blocks = (NN + 127) / 128;
        gemm_kernel<false, true><<<blocks, 512, SMEM>>>(hpre4, W1, b1, (float4*)h_p, NN);
    }
    // 4) BN coefficients
    bn_finalize<<<1, DD>>>(gamma, beta);
    // 5) GEMM2 (+BN+ReLU on input)
    {
        int blocks = (NN + 127) / 128;
        gemm_kernel<true, false><<<blocks, 512, SMEM>>>(h4, W2, b2, (float4*)d_out, NN);
    }
}

// round 13
// speedup vs baseline: 1.8277x; 1.0004x over previous
#include <cuda_runtime.h>
#include <cuda_fp16.h>
#include <cstdint>

#define NN 100000
#define DD 128
#define NE 1600000
#define BN_EPS 1e-5f
#define SCAN_B 512
#define NBLK1 ((NN + SCAN_B - 1) / SCAN_B)   // 196

// Scratch (device globals; float4/uint2 => alignment for wide ld/st)
__device__ float4 g_hpre4[(size_t)NN * 32];   // 51.2 MB
__device__ float4 g_h4[(size_t)NN * 32];      // 51.2 MB
__device__ uint2  g_xh2[(size_t)NN * 32];     // 25.6 MB fp16 mirror of x
__device__ float  g_colsum[DD];
__device__ float  g_colsq[DD];
__device__ float  g_bncoef[2 * DD];
__device__ int    g_is64;
// CSR scratch
__device__ int    g_deg[NN];
__device__ int    g_off[NN];
__device__ int    g_cur[NN];
__device__ int    g_adj[2 * NE];              // 12.8 MB
__device__ int    g_bsum[NBLK1];
__device__ int    g_bpre[NBLK1];

// ---------------------------------------------------------------------------
__global__ void detect_kernel(const long long* __restrict__ ei) {
    long long ok = 1;
    #pragma unroll
    for (int i = 0; i < 16; i++) {
        long long v = ei[i];
        if (v < 0 || v >= NN) ok = 0;
    }
    g_is64 = (int)ok;
}

__device__ __forceinline__ void load_edge(const void* ei_raw, int e, int& s, int& d) {
    if (g_is64) {
        const long long* ei = (const long long*)ei_raw;
        s = (int)ei[e]; d = (int)ei[NE + e];
    } else {
        const int* ei = (const int*)ei_raw;
        s = ei[e]; d = ei[NE + e];
    }
}

// ---------------------------------------------------------------------------
// fused: fp16 mirror of x + zero degrees + zero BN stat accumulators
// ---------------------------------------------------------------------------
__global__ void prep_kernel(const float4* __restrict__ x) {
    int i = blockIdx.x * blockDim.x + threadIdx.x;
    if (i < NN * 32) {
        float4 v = x[i];
        half2 lo = __floats2half2_rn(v.x, v.y);
        half2 hi = __floats2half2_rn(v.z, v.w);
        uint2 u;
        u.x = *reinterpret_cast<unsigned int*>(&lo);
        u.y = *reinterpret_cast<unsigned int*>(&hi);
        g_xh2[i] = u;
    }
    if (i < NN) g_deg[i] = 0;
    if (i < DD) { g_colsum[i] = 0.0f; g_colsq[i] = 0.0f; }
}

// ---------------------------------------------------------------------------
__global__ void hist_kernel(const void* __restrict__ ei_raw) {
    int e = blockIdx.x * blockDim.x + threadIdx.x;
    if (e >= NE) return;
    int s, d; load_edge(ei_raw, e, s, d);
    atomicAdd(&g_deg[d], 1);
    atomicAdd(&g_deg[s], 1);
}

// ---------------------------------------------------------------------------
__global__ void scan_block_kernel() {
    __shared__ int sh[SCAN_B];
    int tid = threadIdx.x;
    int i = blockIdx.x * SCAN_B + tid;
    int v = (i < NN) ? g_deg[i] : 0;
    sh[tid] = v;
    __syncthreads();
    #pragma unroll
    for (int o = 1; o < SCAN_B; o <<= 1) {
        int t = (tid >= o) ? sh[tid - o] : 0;
        __syncthreads();
        sh[tid] += t;
        __syncthreads();
    }
    if (i < NN) g_off[i] = sh[tid] - v;
    if (tid == SCAN_B - 1) g_bsum[blockIdx.x] = sh[tid];
}

__global__ void scan_top_kernel() {
    __shared__ int sh[256];
    int tid = threadIdx.x;
    int v = (tid < NBLK1) ? g_bsum[tid] : 0;
    sh[tid] = v;
    __syncthreads();
    #pragma unroll
    for (int o = 1; o < 256; o <<= 1) {
        int t = (tid >= o) ? sh[tid - o] : 0;
        __syncthreads();
        sh[tid] += t;
        __syncthreads();
    }
    if (tid < NBLK1) g_bpre[tid] = sh[tid] - v;
}

__global__ void scan_add_kernel() {
    int i = blockIdx.x * SCAN_B + threadIdx.x;
    if (i < NN) {
        int o = g_off[i] + g_bpre[blockIdx.x];
        g_off[i] = o;
        g_cur[i] = o;
    }
}

// ---------------------------------------------------------------------------
__global__ void fill_kernel(const void* __restrict__ ei_raw) {
    int e = blockIdx.x * blockDim.x + threadIdx.x;
    if (e >= NE) return;
    int s, d; load_edge(ei_raw, e, s, d);
    int p0 = atomicAdd(&g_cur[d], 1);
    g_adj[p0] = s;
    int p1 = atomicAdd(&g_cur[s], 1);
    g_adj[p1] = d;
}

// ---------------------------------------------------------------------------
// gather: one warp per node; unroll-8 for MLP. fp16 neighbor rows, fp32 accum,
// exact fp32 self-term.
// ---------------------------------------------------------------------------
__global__ void gather_kernel(const float4* __restrict__ x,
                              const float* __restrict__ eps_p) {
    int w = (blockIdx.x * blockDim.x + threadIdx.x) >> 5;
    if (w >= NN) return;
    int lane = threadIdx.x & 31;
    float sc = 2.0f + *eps_p;

    float4 xv = x[(size_t)w * 32 + lane];
    float4 acc = make_float4(xv.x * sc, xv.y * sc, xv.z * sc, xv.w * sc);

    const int* adj = g_adj + g_off[w];
    int deg = g_deg[w];
    int i = 0;
    for (; i + 8 <= deg; i += 8) {
        int n[8];
        #pragma unroll
        for (int j = 0; j < 8; j++) n[j] = adj[i + j];
        uint2 u[8];
        #pragma unroll
        for (int j = 0; j < 8; j++) u[j] = g_xh2[(size_t)n[j] * 32 + lane];
        #pragma unroll
        for (int j = 0; j < 8; j++) {
            float2 a = __half22float2(*reinterpret_cast<half2*>(&u[j].x));
            float2 b = __half22float2(*reinterpret_cast<half2*>(&u[j].y));
            acc.x += a.x; acc.y += a.y; acc.z += b.x; acc.w += b.y;
        }
    }
    for (; i < deg; i++) {
        uint2 u0 = g_xh2[(size_t)adj[i] * 32 + lane];
        float2 a0 = __half22float2(*reinterpret_cast<half2*>(&u0.x));
        float2 b0 = __half22float2(*reinterpret_cast<half2*>(&u0.y));
        acc.x += a0.x; acc.y += a0.y; acc.z += b0.x; acc.w += b0.y;
    }
    g_hpre4[(size_t)w * 32 + lane] = acc;
}

// ---------------------------------------------------------------------------
// register-tiled fp32 GEMM  out[N,128] = f(Z[N,128]) @ W^T + bias
// 256 threads (8 warps), tile 64 rows x 128 cols, K=128 smem-resident.
// smem ~107 KB  =>  2 CTAs resident per SM (16 warps) for latency hiding.
// ---------------------------------------------------------------------------
template <bool BN_IN, bool STATS>
__global__ void __launch_bounds__(256, 2)
gemm_kernel(const float4* __restrict__ Z, const float* __restrict__ W,
            const float* __restrict__ bias, float4* __restrict__ out, int nrows)
{
    extern __shared__ float sm[];
    float* Zs   = sm;                     // [64][132]
    float* Ws   = sm + 64 * 132;          // [128][132], Ws[k*132+j] = W[j][k]
    float* rsum = Ws + 128 * 132;         // [8][128]
    float* rsq  = rsum + 8 * 128;         // [8][128]

    const int tid  = threadIdx.x;
    const int lane = tid & 31;
    const int warp = tid >> 5;
    const int row0 = blockIdx.x * 64;

    #pragma unroll 8
    for (int idx = tid; idx < 128 * 128; idx += 256) {
        int j = idx >> 7, k = idx & 127;
        Ws[k * 132 + j] = W[idx];
    }

    #pragma unroll 8
    for (int i4 = tid; i4 < 64 * 32; i4 += 256) {
        int r = i4 >> 5, c4 = i4 & 31;
        int row = row0 + r;
        float4 v = make_float4(0.f, 0.f, 0.f, 0.f);
        if (row < nrows) {
            v = Z[(size_t)row * 32 + c4];
            if (BN_IN) {
                int c = c4 * 4;
                v.x = fmaxf(fmaf(g_bncoef[c + 0], v.x, g_bncoef[DD + c + 0]), 0.f);
                v.y = fmaxf(fmaf(g_bncoef[c + 1], v.y, g_bncoef[DD + c + 1]), 0.f);
                v.z = fmaxf(fmaf(g_bncoef[c + 2], v.z, g_bncoef[DD + c + 2]), 0.f);
                v.w = fmaxf(fmaf(g_bncoef[c + 3], v.w, g_bncoef[DD + c + 3]), 0.f);
            }
        }
        *reinterpret_cast<float4*>(&Zs[r * 132 + c4 * 4]) = v;
    }
    __syncthreads();

    float4 acc[8];
    #pragma unroll
    for (int i = 0; i < 8; i++) acc[i] = make_float4(0.f, 0.f, 0.f, 0.f);

    const float* zbase = Zs + (warp * 8) * 132;
    #pragma unroll 2
    for (int k = 0; k < 128; k += 4) {
        float4 z[8];
        #pragma unroll
        for (int i = 0; i < 8; i++)
            z[i] = *reinterpret_cast<const float4*>(&zbase[i * 132 + k]);
        #pragma unroll
        for (int kk = 0; kk < 4; kk++) {
            float4 bv = *reinterpret_cast<const float4*>(&Ws[(k + kk) * 132 + lane * 4]);
            #pragma unroll
            for (int i = 0; i < 8; i++) {
                float av = (kk == 0) ? z[i].x : (kk == 1) ? z[i].y : (kk == 2) ? z[i].z : z[i].w;
                acc[i].x = fmaf(av, bv.x, acc[i].x);
                acc[i].y = fmaf(av, bv.y, acc[i].y);
                acc[i].z = fmaf(av, bv.z, acc[i].z);
                acc[i].w = fmaf(av, bv.w, acc[i].w);
            }
        }
    }

    float4 bb = *reinterpret_cast<const float4*>(&bias[lane * 4]);

    float4 s  = make_float4(0.f, 0.f, 0.f, 0.f);
    float4 s2 = make_float4(0.f, 0.f, 0.f, 0.f);
    #pragma unroll
    for (int i = 0; i < 8; i++) {
        int row = row0 + warp * 8 + i;
        if (row < nrows) {
            float4 o;
            o.x = acc[i].x + bb.x;
            o.y = acc[i].y + bb.y;
            o.z = acc[i].z + bb.z;
            o.w = acc[i].w + bb.w;
            out[(size_t)row * 32 + lane] = o;
            if (STATS) {
                s.x += o.x; s.y += o.y; s.z += o.z; s.w += o.w;
                s2.x += o.x * o.x; s2.y += o.y * o.y;
                s2.z += o.z * o.z; s2.w += o.w * o.w;
            }
        }
    }

    if (STATS) {
        *reinterpret_cast<float4*>(&rsum[warp * 128 + lane * 4]) = s;
        *reinterpret_cast<float4*>(&rsq[warp * 128 + lane * 4])  = s2;
        __syncthreads();
        if (tid < 128) {
            float a = 0.f, b2 = 0.f;
            #pragma unroll
            for (int w = 0; w < 8; w++) {
                a  += rsum[w * 128 + tid];
                b2 += rsq[w * 128 + tid];
            }
            atomicAdd(&g_colsum[tid], a);
            atomicAdd(&g_colsq[tid], b2);
        }
    }
}

// ---------------------------------------------------------------------------
__global__ void bn_finalize(const float* __restrict__ gamma, const float* __restrict__ beta) {
    int j = threadIdx.x;
    float invn = 1.0f / (float)NN;
    float mean = g_colsum[j] * invn;
    float var  = g_colsq[j] * invn - mean * mean;
    float a = gamma[j] * rsqrtf(var + BN_EPS);
    g_bncoef[j]      = a;
    g_bncoef[DD + j] = beta[j] - mean * a;
}

// ---------------------------------------------------------------------------
extern "C" void kernel_launch(void* const* d_in, const int* in_sizes, int n_in,
                              void* d_out, int out_size) {
    const float* x     = (const float*)d_in[0];
    const void*  ei    = d_in[1];
    const float* eps   = (const float*)d_in[2];
    const float* W1    = (const float*)d_in[3];
    const float* b1    = (const float*)d_in[4];
    const float* gamma = (const float*)d_in[5];
    const float* beta  = (const float*)d_in[6];
    const float* W2    = (const float*)d_in[7];
    const float* b2    = (const float*)d_in[8];

    void* hpre_p = nullptr;
    void* h_p    = nullptr;
    cudaGetSymbolAddress(&hpre_p, g_hpre4);
    cudaGetSymbolAddress(&h_p, g_h4);
    const float4* hpre4 = (const float4*)hpre_p;
    const float4* h4    = (const float4*)h_p;

    // smem: Zs 64*132 + Ws 128*132 + stats 2*8*128  floats = 107,520 B
    const int SMEM = (64 * 132 + 128 * 132 + 2 * 8 * 128) * (int)sizeof(float);
    cudaFuncSetAttribute(gemm_kernel<false, true>,
                         cudaFuncAttributeMaxDynamicSharedMemorySize, SMEM);
    cudaFuncSetAttribute(gemm_kernel<true, false>,
                         cudaFuncAttributeMaxDynamicSharedMemorySize, SMEM);

    // 0) dtype detect + (fp16 mirror, zero) fused
    detect_kernel<<<1, 1>>>((const long long*)ei);
    prep_kernel<<<(NN * 32 + 255) / 256, 256>>>((const float4*)x);
    // 1) CSR build
    hist_kernel<<<(NE + 255) / 256, 256>>>(ei);
    scan_block_kernel<<<NBLK1, SCAN_B>>>();
    scan_top_kernel<<<1, 256>>>();
    scan_add_kernel<<<NBLK1, SCAN_B>>>();
    fill_kernel<<<(NE + 255) / 256, 256>>>(ei);
    // 2) gather
    gather_kernel<<<(NN * 32 + 255) / 256, 256>>>((const float4*)x, eps);
    // 3) GEMM1 (+bias, +column stats)
    {
        int blocks = (NN + 63) / 64;
        gemm_kernel<false, true><<<blocks, 256, SMEM>>>(hpre4, W1, b1, (float4*)h_p, NN);
    }
    // 4) BN coefficients
    bn_finalize<<<1, DD>>>(gamma, beta);
    // 5) GEMM2 (+BN+ReLU on input)
    {
        int blocks = (NN + 63) / 64;
        gemm_kernel<true, false><<<blocks, 256, SMEM>>>(h4, W2, b2, (float4*)d_out, NN);
    }
}

// round 14
// speedup vs baseline: 1.9268x; 1.0542x over previous
#include <cuda_runtime.h>
#include <cuda_fp16.h>
#include <cstdint>

#define NN 100000
#define DD 128
#define NE 1600000
#define BN_EPS 1e-5f
#define SCAN_B 512
#define NBLK1 ((NN + SCAN_B - 1) / SCAN_B)   // 196

// Scratch (device globals; float4/uint2 => alignment for wide ld/st)
__device__ float4 g_hpre4[(size_t)NN * 32];   // 51.2 MB
__device__ float4 g_h4[(size_t)NN * 32];      // 51.2 MB
__device__ uint2  g_xh2[(size_t)NN * 32];     // 25.6 MB fp16 mirror of x
__device__ float  g_colsum[DD];
__device__ float  g_colsq[DD];
__device__ float  g_bncoef[2 * DD];
__device__ int    g_is64;
// CSR scratch
__device__ int    g_deg[NN];
__device__ int    g_off[NN];
__device__ int    g_cur[NN];
__device__ int    g_adj[2 * NE];              // 12.8 MB
__device__ int    g_bsum[NBLK1];
__device__ int    g_bpre[NBLK1];

// ---------------------------------------------------------------------------
__global__ void detect_kernel(const long long* __restrict__ ei) {
    long long ok = 1;
    #pragma unroll
    for (int i = 0; i < 16; i++) {
        long long v = ei[i];
        if (v < 0 || v >= NN) ok = 0;
    }
    g_is64 = (int)ok;
}

__device__ __forceinline__ void load_edge(const void* ei_raw, int e, int& s, int& d) {
    if (g_is64) {
        const long long* ei = (const long long*)ei_raw;
        s = (int)ei[e]; d = (int)ei[NE + e];
    } else {
        const int* ei = (const int*)ei_raw;
        s = ei[e]; d = ei[NE + e];
    }
}

// ---------------------------------------------------------------------------
// fused: fp16 mirror of x + zero degrees + zero BN stat accumulators
// ---------------------------------------------------------------------------
__global__ void prep_kernel(const float4* __restrict__ x) {
    int i = blockIdx.x * blockDim.x + threadIdx.x;
    if (i < NN * 32) {
        float4 v = x[i];
        half2 lo = __floats2half2_rn(v.x, v.y);
        half2 hi = __floats2half2_rn(v.z, v.w);
        uint2 u;
        u.x = *reinterpret_cast<unsigned int*>(&lo);
        u.y = *reinterpret_cast<unsigned int*>(&hi);
        g_xh2[i] = u;
    }
    if (i < NN) g_deg[i] = 0;
    if (i < DD) { g_colsum[i] = 0.0f; g_colsq[i] = 0.0f; }
}

// ---------------------------------------------------------------------------
__global__ void hist_kernel(const void* __restrict__ ei_raw) {
    int e = blockIdx.x * blockDim.x + threadIdx.x;
    if (e >= NE) return;
    int s, d; load_edge(ei_raw, e, s, d);
    atomicAdd(&g_deg[d], 1);
    atomicAdd(&g_deg[s], 1);
}

// ---------------------------------------------------------------------------
__global__ void scan_block_kernel() {
    __shared__ int sh[SCAN_B];
    int tid = threadIdx.x;
    int i = blockIdx.x * SCAN_B + tid;
    int v = (i < NN) ? g_deg[i] : 0;
    sh[tid] = v;
    __syncthreads();
    #pragma unroll
    for (int o = 1; o < SCAN_B; o <<= 1) {
        int t = (tid >= o) ? sh[tid - o] : 0;
        __syncthreads();
        sh[tid] += t;
        __syncthreads();
    }
    if (i < NN) g_off[i] = sh[tid] - v;
    if (tid == SCAN_B - 1) g_bsum[blockIdx.x] = sh[tid];
}

__global__ void scan_top_kernel() {
    __shared__ int sh[256];
    int tid = threadIdx.x;
    int v = (tid < NBLK1) ? g_bsum[tid] : 0;
    sh[tid] = v;
    __syncthreads();
    #pragma unroll
    for (int o = 1; o < 256; o <<= 1) {
        int t = (tid >= o) ? sh[tid - o] : 0;
        __syncthreads();
        sh[tid] += t;
        __syncthreads();
    }
    if (tid < NBLK1) g_bpre[tid] = sh[tid] - v;
}

__global__ void scan_add_kernel() {
    int i = blockIdx.x * SCAN_B + threadIdx.x;
    if (i < NN) {
        int o = g_off[i] + g_bpre[blockIdx.x];
        g_off[i] = o;
        g_cur[i] = o;
    }
}

// ---------------------------------------------------------------------------
__global__ void fill_kernel(const void* __restrict__ ei_raw) {
    int e = blockIdx.x * blockDim.x + threadIdx.x;
    if (e >= NE) return;
    int s, d; load_edge(ei_raw, e, s, d);
    int p0 = atomicAdd(&g_cur[d], 1);
    g_adj[p0] = s;
    int p1 = atomicAdd(&g_cur[s], 1);
    g_adj[p1] = d;
}

// ---------------------------------------------------------------------------
// gather: one warp per node; unroll-8. fp16 neighbor rows, fp32 accum,
// exact fp32 self-term.
// ---------------------------------------------------------------------------
__global__ void gather_kernel(const float4* __restrict__ x,
                              const float* __restrict__ eps_p) {
    int w = (blockIdx.x * blockDim.x + threadIdx.x) >> 5;
    if (w >= NN) return;
    int lane = threadIdx.x & 31;
    float sc = 2.0f + *eps_p;

    float4 xv = x[(size_t)w * 32 + lane];
    float4 acc = make_float4(xv.x * sc, xv.y * sc, xv.z * sc, xv.w * sc);

    const int* adj = g_adj + g_off[w];
    int deg = g_deg[w];
    int i = 0;
    for (; i + 8 <= deg; i += 8) {
        int n[8];
        #pragma unroll
        for (int j = 0; j < 8; j++) n[j] = adj[i + j];
        uint2 u[8];
        #pragma unroll
        for (int j = 0; j < 8; j++) u[j] = g_xh2[(size_t)n[j] * 32 + lane];
        #pragma unroll
        for (int j = 0; j < 8; j++) {
            float2 a = __half22float2(*reinterpret_cast<half2*>(&u[j].x));
            float2 b = __half22float2(*reinterpret_cast<half2*>(&u[j].y));
            acc.x += a.x; acc.y += a.y; acc.z += b.x; acc.w += b.y;
        }
    }
    for (; i < deg; i++) {
        uint2 u0 = g_xh2[(size_t)adj[i] * 32 + lane];
        float2 a0 = __half22float2(*reinterpret_cast<half2*>(&u0.x));
        float2 b0 = __half22float2(*reinterpret_cast<half2*>(&u0.y));
        acc.x += a0.x; acc.y += a0.y; acc.z += b0.x; acc.w += b0.y;
    }
    g_hpre4[(size_t)w * 32 + lane] = acc;
}

// ---------------------------------------------------------------------------
// FFMA2 (packed f32x2) GEMM  out[N,128] = f(Z[N,128]) @ W^T + bias
// 256 threads (8 warps), tile 64 rows x 128 cols, K=128 smem-resident.
// Z tile stored TRANSPOSED (Zt[k][row]) so LDS.64 yields a packed row-pair.
// Each warp: 8 rows = 4 row-pairs; each lane: 4 cols.  Accumulators are
// 16 x f32x2 pairs.  Inner loop: 16 fma.rn.f32x2 per k (vs 32 FFMA).
// ---------------------------------------------------------------------------
#define ZT_S 66   // Zt row stride (64 rows + 2 pad)

template <bool BN_IN, bool STATS>
__global__ void __launch_bounds__(256, 2)
gemm_kernel(const float4* __restrict__ Z, const float* __restrict__ W,
            const float* __restrict__ bias, float4* __restrict__ out, int nrows)
{
    extern __shared__ float sm[];
    float* Zt   = sm;                     // [128][ZT_S] transposed: Zt[k*ZT_S+row]
    float* Ws   = sm + 128 * ZT_S;        // [128][132], Ws[k*132+j] = W[j][k]
    float* rsum = Ws + 128 * 132;         // [8][128]
    float* rsq  = rsum + 8 * 128;         // [8][128]

    const int tid  = threadIdx.x;
    const int lane = tid & 31;
    const int warp = tid >> 5;
    const int row0 = blockIdx.x * 64;

    #pragma unroll 8
    for (int idx = tid; idx < 128 * 128; idx += 256) {
        int j = idx >> 7, k = idx & 127;
        Ws[k * 132 + j] = W[idx];
    }

    // Z tile -> transposed smem (optionally BN+ReLU on load)
    #pragma unroll 8
    for (int i4 = tid; i4 < 64 * 32; i4 += 256) {
        int r = i4 >> 5, c4 = i4 & 31;
        int row = row0 + r;
        float4 v = make_float4(0.f, 0.f, 0.f, 0.f);
        if (row < nrows) {
            v = Z[(size_t)row * 32 + c4];
            if (BN_IN) {
                int c = c4 * 4;
                v.x = fmaxf(fmaf(g_bncoef[c + 0], v.x, g_bncoef[DD + c + 0]), 0.f);
                v.y = fmaxf(fmaf(g_bncoef[c + 1], v.y, g_bncoef[DD + c + 1]), 0.f);
                v.z = fmaxf(fmaf(g_bncoef[c + 2], v.z, g_bncoef[DD + c + 2]), 0.f);
                v.w = fmaxf(fmaf(g_bncoef[c + 3], v.w, g_bncoef[DD + c + 3]), 0.f);
            }
        }
        int c = c4 * 4;
        Zt[(c + 0) * ZT_S + r] = v.x;
        Zt[(c + 1) * ZT_S + r] = v.y;
        Zt[(c + 2) * ZT_S + r] = v.z;
        Zt[(c + 3) * ZT_S + r] = v.w;
    }
    __syncthreads();

    // acc[c*4+p]: packed pair {row 2p, row 2p+1} of column (lane*4+c)
    unsigned long long acc[16];
    #pragma unroll
    for (int i = 0; i < 16; i++) acc[i] = 0ULL;

    const float* ztbase = Zt + warp * 8;
    #pragma unroll 2
    for (int k = 0; k < 128; k++) {
        // 4 packed row-pairs (broadcast LDS.64, 8B-aligned: warp*8+2p even)
        unsigned long long zp[4];
        #pragma unroll
        for (int p = 0; p < 4; p++)
            zp[p] = *reinterpret_cast<const unsigned long long*>(&ztbase[k * ZT_S + 2 * p]);
        // 4 duplicated weights {w,w}
        float4 bv = *reinterpret_cast<const float4*>(&Ws[k * 132 + lane * 4]);
        unsigned long long wp[4];
        asm("mov.b64 %0, {%1,%1};" : "=l"(wp[0]) : "r"(__float_as_uint(bv.x)));
        asm("mov.b64 %0, {%1,%1};" : "=l"(wp[1]) : "r"(__float_as_uint(bv.y)));
        asm("mov.b64 %0, {%1,%1};" : "=l"(wp[2]) : "r"(__float_as_uint(bv.z)));
        asm("mov.b64 %0, {%1,%1};" : "=l"(wp[3]) : "r"(__float_as_uint(bv.w)));
        #pragma unroll
        for (int c = 0; c < 4; c++) {
            #pragma unroll
            for (int p = 0; p < 4; p++) {
                asm("fma.rn.f32x2 %0, %1, %2, %3;"
                    : "=l"(acc[c * 4 + p])
                    : "l"(zp[p]), "l"(wp[c]), "l"(acc[c * 4 + p]));
            }
        }
    }

    float4 bb = *reinterpret_cast<const float4*>(&bias[lane * 4]);

    float4 s  = make_float4(0.f, 0.f, 0.f, 0.f);
    float4 s2 = make_float4(0.f, 0.f, 0.f, 0.f);
    #pragma unroll
    for (int p = 0; p < 4; p++) {
        float lo[4], hi[4];
        #pragma unroll
        for (int c = 0; c < 4; c++) {
            unsigned int ulo, uhi;
            asm("mov.b64 {%0,%1}, %2;" : "=r"(ulo), "=r"(uhi) : "l"(acc[c * 4 + p]));
            lo[c] = __uint_as_float(ulo);
            hi[c] = __uint_as_float(uhi);
        }
        #pragma unroll
        for (int half = 0; half < 2; half++) {
            int row = row0 + warp * 8 + 2 * p + half;
            if (row < nrows) {
                const float* vv = half ? hi : lo;
                float4 o;
                o.x = vv[0] + bb.x;
                o.y = vv[1] + bb.y;
                o.z = vv[2] + bb.z;
                o.w = vv[3] + bb.w;
                out[(size_t)row * 32 + lane] = o;
                if (STATS) {
                    s.x += o.x; s.y += o.y; s.z += o.z; s.w += o.w;
                    s2.x += o.x * o.x; s2.y += o.y * o.y;
                    s2.z += o.z * o.z; s2.w += o.w * o.w;
                }
            }
        }
    }

    if (STATS) {
        *reinterpret_cast<float4*>(&rsum[warp * 128 + lane * 4]) = s;
        *reinterpret_cast<float4*>(&rsq[warp * 128 + lane * 4])  = s2;
        __syncthreads();
        if (tid < 128) {
            float a = 0.f, b2 = 0.f;
            #pragma unroll
            for (int w = 0; w < 8; w++) {
                a  += rsum[w * 128 + tid];
                b2 += rsq[w * 128 + tid];
            }
            atomicAdd(&g_colsum[tid], a);
            atomicAdd(&g_colsq[tid], b2);
        }
    }
}

// ---------------------------------------------------------------------------
__global__ void bn_finalize(const float* __restrict__ gamma, const float* __restrict__ beta) {
    int j = threadIdx.x;
    float invn = 1.0f / (float)NN;
    float mean = g_colsum[j] * invn;
    float var  = g_colsq[j] * invn - mean * mean;
    float a = gamma[j] * rsqrtf(var + BN_EPS);
    g_bncoef[j]      = a;
    g_bncoef[DD + j] = beta[j] - mean * a;
}

// ---------------------------------------------------------------------------
extern "C" void kernel_launch(void* const* d_in, const int* in_sizes, int n_in,
                              void* d_out, int out_size) {
    const float* x     = (const float*)d_in[0];
    const void*  ei    = d_in[1];
    const float* eps   = (const float*)d_in[2];
    const float* W1    = (const float*)d_in[3];
    const float* b1    = (const float*)d_in[4];
    const float* gamma = (const float*)d_in[5];
    const float* beta  = (const float*)d_in[6];
    const float* W2    = (const float*)d_in[7];
    const float* b2    = (const float*)d_in[8];

    void* hpre_p = nullptr;
    void* h_p    = nullptr;
    cudaGetSymbolAddress(&hpre_p, g_hpre4);
    cudaGetSymbolAddress(&h_p, g_h4);
    const float4* hpre4 = (const float4*)hpre_p;
    const float4* h4    = (const float4*)h_p;

    // smem: Zt 128*66 + Ws 128*132 + stats 2*8*128 floats = 109,568 B (2 CTAs/SM)
    const int SMEM = (128 * ZT_S + 128 * 132 + 2 * 8 * 128) * (int)sizeof(float);
    cudaFuncSetAttribute(gemm_kernel<false, true>,
                         cudaFuncAttributeMaxDynamicSharedMemorySize, SMEM);
    cudaFuncSetAttribute(gemm_kernel<true, false>,
                         cudaFuncAttributeMaxDynamicSharedMemorySize, SMEM);

    // 0) dtype detect + (fp16 mirror, zero) fused
    detect_kernel<<<1, 1>>>((const long long*)ei);
    prep_kernel<<<(NN * 32 + 255) / 256, 256>>>((const float4*)x);
    // 1) CSR build
    hist_kernel<<<(NE + 255) / 256, 256>>>(ei);
    scan_block_kernel<<<NBLK1, SCAN_B>>>();
    scan_top_kernel<<<1, 256>>>();
    scan_add_kernel<<<NBLK1, SCAN_B>>>();
    fill_kernel<<<(NE + 255) / 256, 256>>>(ei);
    // 2) gather
    gather_kernel<<<(NN * 32 + 255) / 256, 256>>>((const float4*)x, eps);
    // 3) GEMM1 (+bias, +column stats)
    {
        int blocks = (NN + 63) / 64;
        gemm_kernel<false, true><<<blocks, 256, SMEM>>>(hpre4, W1, b1, (float4*)h_p, NN);
    }
    // 4) BN coefficients
    bn_finalize<<<1, DD>>>(gamma, beta);
    // 5) GEMM2 (+BN+ReLU on input)
    {
        int blocks = (NN + 63) / 64;
        gemm_kernel<true, false><<<blocks, 256, SMEM>>>(h4, W2, b2, (float4*)d_out, NN);
    }
}